// round 17
// baseline (speedup 1.0000x reference)
#include <cuda_runtime.h>
#include <cuda_bf16.h>
#include <math_constants.h>
#include <cstdint>

#define M_PTS 8192
#define C_DIM 64
#define KNN 20
#define NSPLIT 2
#define SPAN (M_PTS / NSPLIT)   // candidates per split (4096)
#define QB 128                  // queries (=threads) per knn block
#define CT 128                  // candidate tile
#define CHUNK 64                // candidates between cleanups (== surv capacity)

typedef unsigned long long ull;

// ---------------- scratch (device globals; no allocation allowed) -------------
__device__ float g_sq[M_PTS];
__device__ float g_pd[NSPLIT * M_PTS * KNN];
__device__ int   g_pi[NSPLIT * M_PTS * KNN];
__device__ int   g_knn[M_PTS * KNN];
__device__ float g_gb[M_PTS * C_DIM];   // Wb^T f
__device__ float g_u [M_PTS * C_DIM];   // b1 + Wa^T f - Wb^T f

// ---------------- f32x2 helpers ----------------------------------------------
__device__ __forceinline__ ull ffma2(ull a, ull b, ull c) {
    ull d;
    asm("fma.rn.f32x2 %0, %1, %2, %3;" : "=l"(d) : "l"(a), "l"(b), "l"(c));
    return d;
}
__device__ __forceinline__ ull addf2(ull a, ull b) {
    ull d;
    asm("add.rn.f32x2 %0, %1, %2;" : "=l"(d) : "l"(a), "l"(b));
    return d;
}
__device__ __forceinline__ ull pack2(float x, float y) {
    ull r;
    asm("mov.b64 %0, {%1, %2};" : "=l"(r) : "f"(x), "f"(y));
    return r;
}
__device__ __forceinline__ void unpack2(ull v, float& lo, float& hi) {
    asm("mov.b64 {%0, %1}, %2;" : "=f"(lo), "=f"(hi) : "l"(v));
}

// ---------------- kernel 0: squared norms ------------------------------------
__global__ void sq_kernel(const float* __restrict__ pos) {
    int i = blockIdx.x * blockDim.x + threadIdx.x;
    if (i >= M_PTS) return;
    const float4* p4 = reinterpret_cast<const float4*>(pos + i * C_DIM);
    float s = 0.f;
#pragma unroll
    for (int v = 0; v < C_DIM / 4; v++) {
        float4 a = p4[v];
        s += a.x * a.x + a.y * a.y + a.z * a.z + a.w * a.w;
    }
    g_sq[i] = s;
}

// ---------------- kernel 1: partial KNN with batched inserts ------------------
// smem: tile float4[CT*16] | tsq[CT] | sd[CHUNK*QB] | si[CHUNK*QB]
#define SMEM_KNN_BYTES (CT * 64 * 4 + CT * 4 + CHUNK * QB * 4 + CHUNK * QB * 4)
__global__ __launch_bounds__(QB) void knn_part(const float* __restrict__ pos) {
    extern __shared__ char dyn[];
    float4* tile = reinterpret_cast<float4*>(dyn);
    float*  tsq  = reinterpret_cast<float*>(dyn + CT * 64 * 4);
    float*  sd   = reinterpret_cast<float*>(dyn + CT * 64 * 4 + CT * 4);
    int*    si   = reinterpret_cast<int*>(dyn + CT * 64 * 4 + CT * 4 + CHUNK * QB * 4);

    const int tid = threadIdx.x;
    const int q = blockIdx.x * QB + tid;
    const int split = blockIdx.y;
    const int cand0 = split * SPAN;
    const int cand1 = cand0 + SPAN;

    const float4* pos4 = reinterpret_cast<const float4*>(pos);

    // query packed as 32 x f32x2
    ull q2[C_DIM / 2];
#pragma unroll
    for (int v = 0; v < C_DIM / 4; v++) {
        float4 a = pos4[q * (C_DIM / 4) + v];
        q2[2 * v]     = pack2(a.x, a.y);
        q2[2 * v + 1] = pack2(a.z, a.w);
    }
    const float myq = g_sq[q];

    // sorted ascending; bd[KNN-1] = current worst kept (prune threshold)
    float bd[KNN];
    int bi[KNN];
#pragma unroll
    for (int i = 0; i < KNN; i++) { bd[i] = CUDART_INF_F; bi[i] = -1; }

    int cnt = 0;

    for (int t0 = cand0; t0 < cand1; t0 += CT) {
        __syncthreads();
#pragma unroll
        for (int i = 0; i < (CT * (C_DIM / 4)) / QB; i++) {
            int fl = i * QB + tid;
            tile[fl] = pos4[t0 * (C_DIM / 4) + fl];
        }
        tsq[tid] = g_sq[t0 + tid];   // QB == CT
        __syncthreads();

        const ulonglong2* tl = reinterpret_cast<const ulonglong2*>(tile);

        for (int c0 = 0; c0 < CT; c0 += CHUNK) {
            // ---- compute + branchless push over one chunk ----
            for (int j = c0; j < c0 + CHUNK; j += 4) {
                ull a00 = 0, a01 = 0, a10 = 0, a11 = 0;
                ull a20 = 0, a21 = 0, a30 = 0, a31 = 0;
#pragma unroll
                for (int v = 0; v < 16; v++) {
                    ulonglong2 cA = tl[(j + 0) * 16 + v];
                    ulonglong2 cB = tl[(j + 1) * 16 + v];
                    ulonglong2 cC = tl[(j + 2) * 16 + v];
                    ulonglong2 cD = tl[(j + 3) * 16 + v];
                    ull qa = q2[2 * v], qb = q2[2 * v + 1];
                    a00 = ffma2(qa, cA.x, a00);  a01 = ffma2(qb, cA.y, a01);
                    a10 = ffma2(qa, cB.x, a10);  a11 = ffma2(qb, cB.y, a11);
                    a20 = ffma2(qa, cC.x, a20);  a21 = ffma2(qb, cC.y, a21);
                    a30 = ffma2(qa, cD.x, a30);  a31 = ffma2(qb, cD.y, a31);
                }
                float dsc[4];
                {
                    float lo, hi;
                    ull s0 = addf2(a00, a01); unpack2(s0, lo, hi);
                    dsc[0] = fmaf(-2.0f, lo + hi, myq + tsq[j + 0]);
                    ull s1 = addf2(a10, a11); unpack2(s1, lo, hi);
                    dsc[1] = fmaf(-2.0f, lo + hi, myq + tsq[j + 1]);
                    ull s2 = addf2(a20, a21); unpack2(s2, lo, hi);
                    dsc[2] = fmaf(-2.0f, lo + hi, myq + tsq[j + 2]);
                    ull s3 = addf2(a30, a31); unpack2(s3, lo, hi);
                    dsc[3] = fmaf(-2.0f, lo + hi, myq + tsq[j + 3]);
                }
                // branchless push: store to slot cnt, bump cnt on pass
#pragma unroll
                for (int u = 0; u < 4; u++) {
                    sd[cnt * QB + tid] = dsc[u];
                    si[cnt * QB + tid] = t0 + j + u;
                    cnt += (dsc[u] < bd[KNN - 1]) ? 1 : 0;
                }
            }

            // ---- batched cleanup: warp-max iterations of the swap chain ----
            int mx = __reduce_max_sync(0xffffffffu, cnt);
            for (int i = 0; i < mx; i++) {
                bool act = (i < cnt);
                float cd0 = sd[i * QB + tid];
                int ci0 = si[i * QB + tid];
                float cd = act ? cd0 : CUDART_INF_F;
                int ci = act ? ci0 : -1;
                if (cd < bd[KNN - 1]) {
#pragma unroll
                    for (int k = 0; k < KNN; k++) {
                        bool sw = cd < bd[k];
                        float tf = bd[k]; int ti = bi[k];
                        bd[k] = sw ? cd : bd[k];
                        bi[k] = sw ? ci : bi[k];
                        cd = sw ? tf : cd;
                        ci = sw ? ti : ci;
                    }
                }
            }
            cnt = 0;
        }
    }

    const int base = (split * M_PTS + q) * KNN;
#pragma unroll
    for (int i = 0; i < KNN; i++) { g_pd[base + i] = bd[i]; g_pi[base + i] = bi[i]; }
}

// ---------------- kernel 2: merge the partial (sorted) lists ------------------
__global__ __launch_bounds__(128) void knn_merge() {
    int q = blockIdx.x * blockDim.x + threadIdx.x;
    if (q >= M_PTS) return;
    float d[NSPLIT * KNN];
    int id[NSPLIT * KNN];
#pragma unroll
    for (int h = 0; h < NSPLIT; h++)
#pragma unroll
        for (int i = 0; i < KNN; i++) {
            d[h * KNN + i] = g_pd[(h * M_PTS + q) * KNN + i];
            id[h * KNN + i] = g_pi[(h * M_PTS + q) * KNN + i];
        }
    int hp[NSPLIT];
#pragma unroll
    for (int h = 0; h < NSPLIT; h++) hp[h] = 0;
    for (int s = 0; s < KNN; s++) {
        float bm = CUDART_INF_F; int bh = 0; int bid_ = 0x7fffffff;
#pragma unroll
        for (int h = 0; h < NSPLIT; h++) {
            float dv = d[h * KNN + hp[h]];
            int iv = id[h * KNN + hp[h]];
            if (dv < bm || (dv == bm && iv < bid_)) { bm = dv; bh = h; bid_ = iv; }
        }
        g_knn[q * KNN + s] = bid_;
        hp[bh]++;
    }
}

// ---------------- kernel 3: precompute u[p], g[p] -----------------------------
// h_k(q) = relu(u[q] + g[nbr_k]),  g[p] = Wb^T f_p,  u[q] = b1 + Wa^T f_q - g[q]
__global__ __launch_bounds__(256) void pre_kernel(
    const float* __restrict__ f,
    const float* __restrict__ W1, const float* __restrict__ b1)
{
    __shared__ float W1s[128 * 64];
    __shared__ float fs[32 * 64];
    const int tid = threadIdx.x;
    for (int i = tid; i < 128 * 64; i += 256) W1s[i] = W1[i];
    const int p0 = blockIdx.x * 32;
    for (int i = tid; i < 32 * 64; i += 256) fs[i] = f[p0 * 64 + i];
    __syncthreads();

    const int o = tid & 63;
    const int sub = tid >> 6;
    const float bb1 = b1[o];
    for (int pi = sub; pi < 32; pi += 4) {
        float u = bb1, g = 0.f;
#pragma unroll
        for (int c = 0; c < 64; c++) {
            float fv = fs[pi * 64 + c];
            u = fmaf(fv, W1s[c * 64 + o], u);
            g = fmaf(fv, W1s[(64 + c) * 64 + o], g);
        }
        g_gb[(p0 + pi) * 64 + o] = g;
        g_u [(p0 + pi) * 64 + o] = u - g;
    }
}

// ---------------- kernel 4: layer2 + max aggregation --------------------------
// 2 queries per 128-thread block. Thread tile: 5 k-rows x 4 o-cols of H*W2.
// lane mapping within 64-thread query-group: kg = tid&3, og = (tid>>2)&15.
__global__ __launch_bounds__(128) void mlp_kernel(
    const float* __restrict__ W2, const float* __restrict__ b2,
    float* __restrict__ out)
{
    __shared__ float W2s[64 * 64];
    __shared__ float hs[2][KNN * 64];
    __shared__ int sidx[2][KNN];

    const int tid = threadIdx.x;
    const int sub = tid >> 6;
    const int o = tid & 63;
    const int q = blockIdx.x * 2 + sub;

    for (int i = tid; i < 64 * 64; i += 128) W2s[i] = W2[i];
    if (o < KNN) sidx[sub][o] = g_knn[q * KNN + o];
    __syncthreads();

    // phase 1: h = relu(u[q] + g[nbr]) into smem
    const float u = g_u[q * 64 + o];
#pragma unroll
    for (int k = 0; k < KNN; k++) {
        int nb = sidx[sub][k];
        hs[sub][k * 64 + o] = fmaxf(u + g_gb[nb * 64 + o], 0.f);
    }
    __syncthreads();

    // phase 2: tiled H(20x64) * W2(64x64), max over k
    const int kg = tid & 3;          // k-group: rows kg*5 .. kg*5+4
    const int og = (tid >> 2) & 15;  // o-group: cols og*4 .. og*4+3
    float acc[5][4];
#pragma unroll
    for (int kk = 0; kk < 5; kk++)
#pragma unroll
        for (int oo = 0; oo < 4; oo++) acc[kk][oo] = 0.f;

    const float* hb = hs[sub];
#pragma unroll
    for (int c = 0; c < 64; c++) {
        float4 w = *reinterpret_cast<const float4*>(&W2s[c * 64 + og * 4]);
        float hv[5];
#pragma unroll
        for (int kk = 0; kk < 5; kk++) hv[kk] = hb[(kg * 5 + kk) * 64 + c];
#pragma unroll
        for (int kk = 0; kk < 5; kk++) {
            acc[kk][0] = fmaf(hv[kk], w.x, acc[kk][0]);
            acc[kk][1] = fmaf(hv[kk], w.y, acc[kk][1]);
            acc[kk][2] = fmaf(hv[kk], w.z, acc[kk][2]);
            acc[kk][3] = fmaf(hv[kk], w.w, acc[kk][3]);
        }
    }
    // per-thread max over its 5 k
    float pm[4];
#pragma unroll
    for (int oo = 0; oo < 4; oo++) {
        float m = acc[0][oo];
#pragma unroll
        for (int kk = 1; kk < 5; kk++) m = fmaxf(m, acc[kk][oo]);
        pm[oo] = m;
    }
    // reduce across the 4 kg lanes (lanes differing in bits 0-1, same warp)
#pragma unroll
    for (int oo = 0; oo < 4; oo++) {
        pm[oo] = fmaxf(pm[oo], __shfl_xor_sync(0xffffffffu, pm[oo], 1));
        pm[oo] = fmaxf(pm[oo], __shfl_xor_sync(0xffffffffu, pm[oo], 2));
    }
    if (kg == 0) {
        float4 bv = *reinterpret_cast<const float4*>(&b2[og * 4]);
        float4 res = make_float4(pm[0] + bv.x, pm[1] + bv.y,
                                 pm[2] + bv.z, pm[3] + bv.w);
        *reinterpret_cast<float4*>(&out[q * 64 + og * 4]) = res;
    }
}

// ---------------- launch -------------------------------------------------------
extern "C" void kernel_launch(void* const* d_in, const int* in_sizes, int n_in,
                              void* d_out, int out_size)
{
    const float* pos  = (const float*)d_in[0];
    const float* feat = (const float*)d_in[1];
    const float* W1   = (const float*)d_in[2];
    const float* b1   = (const float*)d_in[3];
    const float* W2   = (const float*)d_in[4];
    const float* b2   = (const float*)d_in[5];
    float* out = (float*)d_out;

    sq_kernel<<<(M_PTS + 255) / 256, 256>>>(pos);

    cudaFuncSetAttribute(knn_part, cudaFuncAttributeMaxDynamicSharedMemorySize,
                         SMEM_KNN_BYTES);
    dim3 kg(M_PTS / QB, NSPLIT);
    knn_part<<<kg, QB, SMEM_KNN_BYTES>>>(pos);

    knn_merge<<<(M_PTS + 127) / 128, 128>>>();

    pre_kernel<<<M_PTS / 32, 256>>>(feat, W1, b1);

    mlp_kernel<<<M_PTS / 2, 128>>>(W2, b2, out);
}